// round 9
// baseline (speedup 1.0000x reference)
#include <cuda_runtime.h>
#include <math.h>
#include <stdint.h>

#define BATCH 4
#define SEQ   2048
#define CDIM  1024
#define HD    128
#define QKN   256
#define SCALE_F 0.08838834764831845f

// attention tiling
#define BQA 32
#define BKA 64
#define NQTA (SEQ/BQA)
#define KSS 132                  // K smem stride
#define VSS 136                  // V smem stride
#define OBS 132                  // O combine buffer stride
#define KS_TILE (BKA*KSS)        // 8448
#define ML_OFF (4*KS_TILE + 2*BKA*VSS)      // K(4 tiles) + V(2 bufs)
#define ATT_F  (ML_OFF + 384)
#define ATT_SMEM (ATT_F*4)       // ~202 KB

// ---------------- scratch ----------------------------------------------------
__device__ __align__(16) float g_Q[BATCH*SEQ*QKN];   // pre-scaled, tf32-rounded
__device__ __align__(16) float g_K[BATCH*SEQ*QKN];   // tf32-rounded
__device__ __align__(16) float g_V[BATCH*SEQ*HD];    // tf32-rounded

// ---------------- helpers ----------------------------------------------------
__device__ __forceinline__ uint32_t tf32u(float x) {
  uint32_t y; asm("cvt.rna.tf32.f32 %0, %1;" : "=r"(y) : "f"(x)); return y;
}
__device__ __forceinline__ float tf32f(float x) { return __uint_as_float(tf32u(x)); }

__device__ __forceinline__ void mma8(float& c0, float& c1, float& c2, float& c3,
                                     uint32_t a0, uint32_t a1, uint32_t a2, uint32_t a3,
                                     uint32_t b0, uint32_t b1) {
  asm volatile(
    "mma.sync.aligned.m16n8k8.row.col.f32.tf32.tf32.f32 "
    "{%0,%1,%2,%3}, {%4,%5,%6,%7}, {%8,%9}, {%0,%1,%2,%3};\n"
    : "+f"(c0), "+f"(c1), "+f"(c2), "+f"(c3)
    : "r"(a0), "r"(a1), "r"(a2), "r"(a3), "r"(b0), "r"(b1));
}

__device__ __forceinline__ void cpa16(uint32_t dst, const void* src) {
  asm volatile("cp.async.cg.shared.global [%0], [%1], 16;" :: "r"(dst), "l"(src));
}
#define CP_COMMIT() asm volatile("cp.async.commit_group;" ::: "memory")

// ---------------- fused tf32 projection GEMMs (R5 config: 64x64, static smem) -
#define AST 36
#define BST 72
__global__ __launch_bounds__(128) void gemm_all(
    const float* __restrict__ q, const float* __restrict__ k, const float* __restrict__ v,
    const float* __restrict__ Wq, const float* __restrict__ Wk, const float* __restrict__ Wv) {
  __shared__ float As[2][64*AST];
  __shared__ float Bs[2][32*BST];

  int bid = blockIdx.x;
  const float *A, *Bm; float* C; int N, mBase, nBase; float scale = 1.f;
  if (bid < 512)       { A=q; Bm=Wq; C=g_Q; N=QKN; mBase=(bid>>2)<<6;        nBase=(bid&3)<<6; scale=SCALE_F; }
  else if (bid < 1024) { int l=bid-512;  A=k; Bm=Wk; C=g_K; N=QKN; mBase=(l>>2)<<6; nBase=(l&3)<<6; }
  else                 { int l=bid-1024; A=v; Bm=Wv; C=g_V; N=HD;  mBase=(l>>1)<<6; nBase=(l&1)<<6; }

  int tid = threadIdx.x, lane = tid & 31, wid = tid >> 5;
  int wm = wid & 1, wn = wid >> 1;
  int gID = lane >> 2, tig = lane & 3;
  int arow = tid >> 3, acol = (tid & 7) << 2;
  int brow = tid >> 4, bcol = (tid & 15) << 2;

  float4 ra[4], rb[4];
  auto ldt = [&](int it) {
    int k0 = it << 5;
    #pragma unroll
    for (int p = 0; p < 4; ++p)
      ra[p] = *(const float4*)(A + (size_t)(mBase + arow + 16*p)*CDIM + k0 + acol);
    #pragma unroll
    for (int p = 0; p < 4; ++p)
      rb[p] = *(const float4*)(Bm + (size_t)(k0 + brow + 8*p)*N + nBase + bcol);
  };
  auto stt = [&](int buf) {
    #pragma unroll
    for (int p = 0; p < 4; ++p) {
      float* d = As[buf] + (arow + 16*p)*AST + acol;
      d[0]=tf32f(ra[p].x); d[1]=tf32f(ra[p].y); d[2]=tf32f(ra[p].z); d[3]=tf32f(ra[p].w);
    }
    #pragma unroll
    for (int p = 0; p < 4; ++p) {
      float* d = Bs[buf] + (brow + 8*p)*BST + bcol;
      d[0]=tf32f(rb[p].x); d[1]=tf32f(rb[p].y); d[2]=tf32f(rb[p].z); d[3]=tf32f(rb[p].w);
    }
  };

  float c[8][4] = {};
  ldt(0); stt(0); __syncthreads();
  for (int it = 0; it < 32; ++it) {
    int cb = it & 1;
    if (it < 31) ldt(it + 1);
    #pragma unroll
    for (int ks = 0; ks < 4; ++ks) {
      uint32_t a[2][4], bf[4][2];
      #pragma unroll
      for (int mt = 0; mt < 2; ++mt) {
        const float* ap = As[cb] + (wm*32 + mt*16 + gID)*AST + ks*8;
        a[mt][0] = __float_as_uint(ap[tig]);
        a[mt][1] = __float_as_uint(ap[8*AST + tig]);
        a[mt][2] = __float_as_uint(ap[tig + 4]);
        a[mt][3] = __float_as_uint(ap[8*AST + tig + 4]);
      }
      #pragma unroll
      for (int nt = 0; nt < 4; ++nt) {
        int col = wn*32 + nt*8 + gID;
        bf[nt][0] = __float_as_uint(Bs[cb][(ks*8 + tig)*BST + col]);
        bf[nt][1] = __float_as_uint(Bs[cb][(ks*8 + tig + 4)*BST + col]);
      }
      #pragma unroll
      for (int mt = 0; mt < 2; ++mt)
        #pragma unroll
        for (int nt = 0; nt < 4; ++nt)
          mma8(c[mt*4+nt][0], c[mt*4+nt][1], c[mt*4+nt][2], c[mt*4+nt][3],
               a[mt][0], a[mt][1], a[mt][2], a[mt][3], bf[nt][0], bf[nt][1]);
    }
    if (it < 31) { stt(cb ^ 1); __syncthreads(); }
  }
  #pragma unroll
  for (int mt = 0; mt < 2; ++mt)
    #pragma unroll
    for (int nt = 0; nt < 4; ++nt) {
      int r0 = mBase + wm*32 + mt*16 + gID;
      int col = nBase + wn*32 + nt*8 + 2*tig;
      float* f = c[mt*4+nt];
      *(float2*)(C + (size_t)r0*N + col)     = make_float2(tf32f(f[0]*scale), tf32f(f[1]*scale));
      *(float2*)(C + (size_t)(r0+8)*N + col) = make_float2(tf32f(f[2]*scale), tf32f(f[3]*scale));
    }
}

// ---------------- fused differential flash attention -------------------------
// 256 threads = 8 warps: stream = wid&1, rowgrp = (wid>>1)&1, colgrp = wid>>2.
// Warp: 16 rows x own 32 score-cols, private (m,l), full 128-col O.
// K AND V double-buffered; ONE barrier per kt; P stays in registers and is
// re-fragmented for PV via shuffle transpose (no smem round trip).
__global__ __launch_bounds__(256, 1) void attn_tc(
    float* __restrict__ out,
    const float* __restrict__ lq1, const float* __restrict__ lk1,
    const float* __restrict__ lq2, const float* __restrict__ lk2) {
  extern __shared__ float sm[];
  float* Ks  = sm;                     // [db][stream][64][KSS]
  float* Vs  = sm + 4*KS_TILE;         // [db][64][VSS]
  float* mbuf = sm + ML_OFF;           // [8][16]
  float* lbuf = mbuf + 128;            // [8][16]
  float* lfin = lbuf + 128;            // [4][16]

  int bid = blockIdx.x;
  int b, qt;
  if (bid < 148) { b = bid & 3; qt = (NQTA-1) - (bid >> 2); }
  else           { int r = bid - 148; b = r & 3; qt = r >> 2; }
  int q0 = qt * BQA;

  int tid = threadIdx.x, lane = tid & 31, wid = tid >> 5;
  int stream = wid & 1, rowgrp = (wid >> 1) & 1, colgrp = wid >> 2;
  int mrow = rowgrp*16, scol = colgrp*32;
  int gID = lane >> 2, tig = lane & 3;
  int kt_end = min((q0 + BQA) >> 6, (SEQ-1) >> 6);

  uint32_t KsU = (uint32_t)__cvta_generic_to_shared(Ks);
  uint32_t VsU = (uint32_t)__cvta_generic_to_shared(Vs);

  auto issueKV = [&](int ktile, int dbuf) {
    int j0 = ktile * BKA;
    #pragma unroll
    for (int i = 0; i < 16; ++i) {
      int idx = tid + i*256;
      int st  = idx >> 11;
      int rem = idx & 2047;
      int j = rem >> 5, d4 = rem & 31;
      const float* src = g_K + ((size_t)(b*SEQ + j0 + j))*QKN + st*HD + (d4 << 2);
      uint32_t dst = KsU + (((dbuf*2 + st)*KS_TILE) + j*KSS + (d4 << 2))*4u;
      cpa16(dst, src);
    }
    #pragma unroll
    for (int i = 0; i < 8; ++i) {
      int idx = tid + i*256;
      int j = idx >> 5, d4 = idx & 31;
      const float* src = g_V + ((size_t)(b*SEQ + j0 + j))*HD + (d4 << 2);
      uint32_t dst = VsU + (dbuf*BKA*VSS + j*VSS + (d4 << 2))*4u;
      cpa16(dst, src);
    }
  };

  // Q fragments (16 rows x this stream's 128 dims), kept in regs.
  uint32_t qf[16][4];
  {
    const float* qb = g_Q + ((size_t)(b*SEQ + q0 + mrow))*QKN + stream*HD;
    #pragma unroll
    for (int ks = 0; ks < 16; ++ks) {
      qf[ks][0] = __float_as_uint(qb[(size_t)gID*QKN     + ks*8 + tig]);
      qf[ks][1] = __float_as_uint(qb[(size_t)(gID+8)*QKN + ks*8 + tig]);
      qf[ks][2] = __float_as_uint(qb[(size_t)gID*QKN     + ks*8 + tig + 4]);
      qf[ks][3] = __float_as_uint(qb[(size_t)(gID+8)*QKN + ks*8 + tig + 4]);
    }
  }

  float O[16][4] = {};
  float m_lo = -1e30f, m_hi = -1e30f, l_lo = 0.f, l_hi = 0.f;

  issueKV(0, 0); CP_COMMIT();

  for (int kt = 0; kt <= kt_end; ++kt) {
    int db = kt & 1;
    asm volatile("cp.async.wait_group 0;" ::: "memory");   // K(kt)+V(kt) landed
    __syncthreads();   // staged data visible to all; db^1 readers (kt-1) done
    if (kt < kt_end) { issueKV(kt + 1, db ^ 1); CP_COMMIT(); }

    // scores over own 32 cols (Q pre-scaled)
    const float* Kb = Ks + (db*2 + stream)*KS_TILE;
    float S[4][4] = {};
    #pragma unroll
    for (int ks = 0; ks < 16; ++ks) {
      #pragma unroll
      for (int nt = 0; nt < 4; ++nt) {
        int jl = scol + nt*8 + gID;
        uint32_t b0 = __float_as_uint(Kb[jl*KSS + ks*8 + tig]);
        uint32_t b1 = __float_as_uint(Kb[jl*KSS + ks*8 + tig + 4]);
        mma8(S[nt][0], S[nt][1], S[nt][2], S[nt][3],
             qf[ks][0], qf[ks][1], qf[ks][2], qf[ks][3], b0, b1);
      }
    }

    // mask + warp-private row max over own slice
    int j0k = kt * BKA;
    int r_lo = q0 + mrow + gID, r_hi = r_lo + 8;
    float mx0 = -1e30f, mx1 = -1e30f;
    #pragma unroll
    for (int nt = 0; nt < 4; ++nt) {
      int jb = j0k + scol + nt*8 + 2*tig;
      S[nt][0] = (jb     <= r_lo + 1) ? S[nt][0] : -1e30f;
      S[nt][1] = (jb + 1 <= r_lo + 1) ? S[nt][1] : -1e30f;
      S[nt][2] = (jb     <= r_hi + 1) ? S[nt][2] : -1e30f;
      S[nt][3] = (jb + 1 <= r_hi + 1) ? S[nt][3] : -1e30f;
      mx0 = fmaxf(mx0, fmaxf(S[nt][0], S[nt][1]));
      mx1 = fmaxf(mx1, fmaxf(S[nt][2], S[nt][3]));
    }
    mx0 = fmaxf(mx0, __shfl_xor_sync(0xffffffffu, mx0, 1));
    mx0 = fmaxf(mx0, __shfl_xor_sync(0xffffffffu, mx0, 2));
    mx1 = fmaxf(mx1, __shfl_xor_sync(0xffffffffu, mx1, 1));
    mx1 = fmaxf(mx1, __shfl_xor_sync(0xffffffffu, mx1, 2));
    float mn0 = fmaxf(m_lo, mx0), mn1 = fmaxf(m_hi, mx1);
    float al0 = __expf(m_lo - mn0), al1 = __expf(m_hi - mn1);
    m_lo = mn0; m_hi = mn1;

    // p = valid ? exp(s-m) : 0, rounded to tf32, kept in regs
    uint32_t pL[4][2], pH[4][2];
    float s0 = 0.f, s1 = 0.f;
    #pragma unroll
    for (int nt = 0; nt < 4; ++nt) {
      int jb = j0k + scol + nt*8 + 2*tig;
      float p00 = (jb     <= r_lo + 1) ? __expf(S[nt][0] - mn0) : 0.f;
      float p01 = (jb + 1 <= r_lo + 1) ? __expf(S[nt][1] - mn0) : 0.f;
      float p10 = (jb     <= r_hi + 1) ? __expf(S[nt][2] - mn1) : 0.f;
      float p11 = (jb + 1 <= r_hi + 1) ? __expf(S[nt][3] - mn1) : 0.f;
      s0 += p00 + p01; s1 += p10 + p11;
      pL[nt][0] = tf32u(p00); pL[nt][1] = tf32u(p01);
      pH[nt][0] = tf32u(p10); pH[nt][1] = tf32u(p11);
    }
    s0 += __shfl_xor_sync(0xffffffffu, s0, 1); s0 += __shfl_xor_sync(0xffffffffu, s0, 2);
    s1 += __shfl_xor_sync(0xffffffffu, s1, 1); s1 += __shfl_xor_sync(0xffffffffu, s1, 2);
    l_lo = l_lo*al0 + s0;
    l_hi = l_hi*al1 + s1;
    #pragma unroll
    for (int nt = 0; nt < 16; ++nt) {
      O[nt][0] *= al0; O[nt][1] *= al0; O[nt][2] *= al1; O[nt][3] *= al1;
    }

    // O += P @ V: shuffle-transpose C-frags -> A-frags, no smem
    const float* Vb = Vs + db*BKA*VSS;
    int srcA = (gID << 2) | (tig >> 1);
    int sel  = tig & 1;
    #pragma unroll
    for (int kk = 0; kk < 4; ++kk) {
      uint32_t u0 = __shfl_sync(0xffffffffu, pL[kk][0], srcA);
      uint32_t u1 = __shfl_sync(0xffffffffu, pL[kk][1], srcA);
      uint32_t pa0 = sel ? u1 : u0;
      uint32_t u2 = __shfl_sync(0xffffffffu, pH[kk][0], srcA);
      uint32_t u3 = __shfl_sync(0xffffffffu, pH[kk][1], srcA);
      uint32_t pa1 = sel ? u3 : u2;
      uint32_t u4 = __shfl_sync(0xffffffffu, pL[kk][0], srcA + 2);
      uint32_t u5 = __shfl_sync(0xffffffffu, pL[kk][1], srcA + 2);
      uint32_t pa2 = sel ? u5 : u4;
      uint32_t u6 = __shfl_sync(0xffffffffu, pH[kk][0], srcA + 2);
      uint32_t u7 = __shfl_sync(0xffffffffu, pH[kk][1], srcA + 2);
      uint32_t pa3 = sel ? u7 : u6;
      #pragma unroll
      for (int nt = 0; nt < 16; ++nt) {
        int col = nt*8 + gID;
        uint32_t b0 = __float_as_uint(Vb[(scol + kk*8 + tig)*VSS + col]);
        uint32_t b1 = __float_as_uint(Vb[(scol + kk*8 + tig + 4)*VSS + col]);
        mma8(O[nt][0], O[nt][1], O[nt][2], O[nt][3], pa0, pa1, pa2, pa3, b0, b1);
      }
    }
  } // kt

  // ---- final combine: column halves, then streams ----
  if (tig == 0) {
    mbuf[wid*16 + gID] = m_lo;  mbuf[wid*16 + gID + 8] = m_hi;
    lbuf[wid*16 + gID] = l_lo;  lbuf[wid*16 + gID + 8] = l_hi;
  }
  __syncthreads();
  int peer = wid ^ 4;
  float pm_lo = mbuf[peer*16 + gID], pm_hi = mbuf[peer*16 + gID + 8];
  float pl_lo = lbuf[peer*16 + gID], pl_hi = lbuf[peer*16 + gID + 8];
  float mf_lo = fmaxf(m_lo, pm_lo),  mf_hi = fmaxf(m_hi, pm_hi);
  float af_lo = __expf(m_lo - mf_lo), af_hi = __expf(m_hi - mf_hi);
  float lf_lo = af_lo*l_lo + __expf(pm_lo - mf_lo)*pl_lo;
  float lf_hi = af_hi*l_hi + __expf(pm_hi - mf_hi)*pl_hi;
  if (colgrp == 0 && tig == 0) {
    lfin[(stream*2 + rowgrp)*16 + gID]     = lf_lo;
    lfin[(stream*2 + rowgrp)*16 + gID + 8] = lf_hi;
  }
  float* Ob = Ks + (stream*2 + rowgrp)*(16*OBS);   // reuse K smem
  if (colgrp == 0) {
    #pragma unroll
    for (int nt = 0; nt < 16; ++nt) {
      int col = nt*8 + 2*tig;
      *(float2*)(Ob + gID*OBS + col)     = make_float2(af_lo*O[nt][0], af_lo*O[nt][1]);
      *(float2*)(Ob + (gID+8)*OBS + col) = make_float2(af_hi*O[nt][2], af_hi*O[nt][3]);
    }
  }
  __syncthreads();
  if (colgrp == 1) {
    #pragma unroll
    for (int nt = 0; nt < 16; ++nt) {
      int col = nt*8 + 2*tig;
      float2* p0 = (float2*)(Ob + gID*OBS + col);
      float2* p1 = (float2*)(Ob + (gID+8)*OBS + col);
      float2 t0 = *p0, t1 = *p1;
      t0.x += af_lo*O[nt][0]; t0.y += af_lo*O[nt][1];
      t1.x += af_hi*O[nt][2]; t1.y += af_hi*O[nt][3];
      *p0 = t0; *p1 = t1;
    }
  }
  __syncthreads();
  if (stream == 0) {
    float d1 = 0.f, d2 = 0.f;
    #pragma unroll
    for (int i = 0; i < 4; ++i) {
      int ix = lane + i*32;
      d1 += lq1[ix]*lk1[ix];
      d2 += lq2[ix]*lk2[ix];
    }
    #pragma unroll
    for (int off = 16; off; off >>= 1) {
      d1 += __shfl_xor_sync(0xffffffffu, d1, off);
      d2 += __shfl_xor_sync(0xffffffffu, d2, off);
    }
    float lbd = __expf(d1) - __expf(d2) + 0.8f;

    const float* Ob0 = Ks + (0*2 + rowgrp)*(16*OBS);
    const float* Ob1 = Ks + (1*2 + rowgrp)*(16*OBS);
    const float* lf0 = lfin + (0*2 + rowgrp)*16;
    const float* lf1 = lfin + (1*2 + rowgrp)*16;
    for (int idx = lane; idx < 16*64; idx += 32) {
      int r = idx >> 6, cc = (idx & 63) + colgrp*64;
      float o = Ob0[r*OBS + cc] / lf0[r] - lbd * (Ob1[r*OBS + cc] / lf1[r]);
      out[((size_t)(b*SEQ + q0 + mrow + r))*HD + cc] = o;
    }
  }
}

// ---------------- launch ------------------------------------------------------
extern "C" void kernel_launch(void* const* d_in, const int* in_sizes, int n_in,
                              void* d_out, int out_size) {
  const float* q   = (const float*)d_in[0];
  const float* k   = (const float*)d_in[1];
  const float* v   = (const float*)d_in[2];
  const float* Wq  = (const float*)d_in[3];
  const float* Wk  = (const float*)d_in[4];
  const float* Wv  = (const float*)d_in[5];
  const float* lq1 = (const float*)d_in[6];
  const float* lk1 = (const float*)d_in[7];
  const float* lq2 = (const float*)d_in[8];
  const float* lk2 = (const float*)d_in[9];
  float* out = (float*)d_out;

  cudaFuncSetAttribute(attn_tc, cudaFuncAttributeMaxDynamicSharedMemorySize, ATT_SMEM);

  gemm_all<<<1280, 128>>>(q, k, v, Wq, Wk, Wv);
  attn_tc<<<4*NQTA, 256, ATT_SMEM>>>(out, lq1, lk1, lq2, lk2);
}